// round 1
// baseline (speedup 1.0000x reference)
#include <cuda_runtime.h>
#include <math.h>

#define T_SEQ 256
#define E_DIM 1024
#define H_DIM 2048
#define LATD  512
#define CLSD  512
#define MIXD  384
#define VJD   64

#define NBLK  148
#define NTHR  512
#define NWARPS (NBLK * (NTHR/32))
#define GRID_THREADS (NBLK * NTHR)

// output layout (float32): lat_f_full(640), lat_r_full(640), rec_f(256*1024),
// rec_r(256*1024), emb_f(256*1024), emb_r(256*1024)
#define OFF_LATF 0
#define OFF_LATR 640
#define OFF_RECF 1280
#define OFF_RECR (1280 + T_SEQ*E_DIM)
#define OFF_EMBF (1280 + 2*T_SEQ*E_DIM)
#define OFF_EMBR (1280 + 3*T_SEQ*E_DIM)

// persistent scratch
__device__ float g_h[2][2][H_DIM];     // encoder hidden ping-pong [parity][dir][j]
__device__ float g_c[2][H_DIM];        // encoder cell [dir][j] (warp-owned, in place)
__device__ float g_common[CLSD];
__device__ float g_h0[2][E_DIM];       // decoder initial state [dir][e]
__device__ float g_dh[2][2][E_DIM];    // decoder hidden ping-pong
__device__ float g_dp[2][2][E_DIM];    // decoder prev-output ping-pong
__device__ float g_dc[2][E_DIM];       // decoder cell

__device__ unsigned int g_bar_arrive;
__device__ volatile unsigned int g_bar_release;

__global__ void init_kernel() { g_bar_arrive = 0u; g_bar_release = 0u; }

__device__ __forceinline__ float sigf(float x) { return 1.0f / (1.0f + expf(-x)); }

__device__ __forceinline__ void grid_sync(unsigned int& round) {
    __threadfence();           // publish my writes (gpu scope; also invalidates L1)
    __syncthreads();
    if (threadIdx.x == 0) {
        round++;
        unsigned int a = atomicAdd(&g_bar_arrive, 1u) + 1u;
        if (a == round * (unsigned)NBLK) {
            g_bar_release = round;
        } else {
            while (g_bar_release < round) { }
        }
    }
    __syncthreads();
}

__device__ __forceinline__ float warp_sum(float v) {
    #pragma unroll
    for (int off = 16; off; off >>= 1) v += __shfl_xor_sync(0xFFFFFFFFu, v, off);
    return v;
}

__global__ __launch_bounds__(NTHR, 1)
void net_kernel(const int* __restrict__ x, const int* __restrict__ Vg, const int* __restrict__ Jg,
                const float* __restrict__ emb, const float* __restrict__ emb_Vg, const float* __restrict__ emb_Jg,
                const float* __restrict__ enc_Wih, const float* __restrict__ enc_Whh,
                const float* __restrict__ enc_bih, const float* __restrict__ enc_bhh,
                const float* __restrict__ cls_W, const float* __restrict__ cls_b,
                const float* __restrict__ latf_W, const float* __restrict__ latf_b,
                const float* __restrict__ latr_W, const float* __restrict__ latr_b,
                const float* __restrict__ mix_W, const float* __restrict__ mix_b,
                const float* __restrict__ recf_Wih, const float* __restrict__ recf_Whh,
                const float* __restrict__ recf_bih, const float* __restrict__ recf_bhh,
                const float* __restrict__ recr_Wih, const float* __restrict__ recr_Whh,
                const float* __restrict__ recr_bih, const float* __restrict__ recr_bhh,
                float* __restrict__ out)
{
    __shared__ float sbuf[6144];   // 24 KB staging
    unsigned int round = 0;

    const int tid  = threadIdx.x;
    const int gtid = blockIdx.x * NTHR + tid;
    const int lane = tid & 31;
    const int wid  = gtid >> 5;   // global warp id

    // ---------------- Phase A: embedding gather + output edges + state init ----
    for (int idx = gtid; idx < T_SEQ * E_DIM; idx += GRID_THREADS) {
        int t = idx >> 10, e = idx & 1023;
        float v = emb[x[t] * E_DIM + e];
        out[OFF_EMBF + idx] = v;
        out[OFF_EMBR + (T_SEQ - 1 - t) * E_DIM + e] = v;
    }
    for (int e = gtid; e < E_DIM; e += GRID_THREADS) {
        float e0 = emb[e];             // emb[X_IDX=0] (start)
        float e1 = emb[E_DIM + e];     // emb[B_IDX=1] (stop)
        out[OFF_RECF + e] = e1;                      // rec_f[0]   = stop
        out[OFF_RECF + 255 * E_DIM + e] = e0;        // rec_f[255] = start
        out[OFF_RECR + e] = e0;                      // rec_r[0]   = start
        out[OFF_RECR + 255 * E_DIM + e] = e1;        // rec_r[255] = stop
    }
    {
        float* hflat = &g_h[0][0][0];
        float* cflat = &g_c[0][0];
        for (int j = gtid; j < 2 * H_DIM; j += GRID_THREADS) { hflat[j] = 0.f; cflat[j] = 0.f; }
    }
    grid_sync(round);

    // ---------------- Encoder: 256 steps, both directions share weights --------
    float* sxf = sbuf;            // 1024
    float* sxr = sbuf + 1024;     // 1024
    float* shf = sbuf + 2048;     // 2048
    float* shr = sbuf + 4096;     // 2048
    for (int t = 0; t < T_SEQ; ++t) {
        const int p = t & 1;
        for (int i = tid; i < E_DIM; i += NTHR) {
            sxf[i] = out[OFF_EMBF + t * E_DIM + i];
            sxr[i] = out[OFF_EMBR + t * E_DIM + i];
        }
        for (int i = tid; i < H_DIM; i += NTHR) {
            shf[i] = g_h[p][0][i];
            shr[i] = g_h[p][1][i];
        }
        __syncthreads();

        const float4* xf4 = (const float4*)sxf;
        const float4* xr4 = (const float4*)sxr;
        const float4* hf4 = (const float4*)shf;
        const float4* hr4 = (const float4*)shr;

        for (int j = wid; j < H_DIM; j += NWARPS) {
            float gf[4], gr[4];
            #pragma unroll
            for (int gx = 0; gx < 4; ++gx) {
                const int row = gx * H_DIM + j;
                const float4* wi = (const float4*)(enc_Wih + (size_t)row * E_DIM);
                const float4* wh = (const float4*)(enc_Whh + (size_t)row * H_DIM);
                float af = 0.f, ar = 0.f;
                #pragma unroll 4
                for (int k = lane; k < E_DIM / 4; k += 32) {
                    float4 w = wi[k];
                    float4 a = xf4[k]; af += w.x*a.x + w.y*a.y + w.z*a.z + w.w*a.w;
                    float4 b = xr4[k]; ar += w.x*b.x + w.y*b.y + w.z*b.z + w.w*b.w;
                }
                #pragma unroll 4
                for (int k = lane; k < H_DIM / 4; k += 32) {
                    float4 w = wh[k];
                    float4 a = hf4[k]; af += w.x*a.x + w.y*a.y + w.z*a.z + w.w*a.w;
                    float4 b = hr4[k]; ar += w.x*b.x + w.y*b.y + w.z*b.z + w.w*b.w;
                }
                af = warp_sum(af);
                ar = warp_sum(ar);
                float bias = enc_bih[row] + enc_bhh[row];
                gf[gx] = af + bias;
                gr[gx] = ar + bias;
            }
            if (lane == 0) {
                float cf = g_c[0][j];
                float cf2 = sigf(gf[1]) * cf + sigf(gf[0]) * tanhf(gf[2]);
                g_c[0][j] = cf2;
                g_h[p ^ 1][0][j] = sigf(gf[3]) * tanhf(cf2);

                float cr = g_c[1][j];
                float cr2 = sigf(gr[1]) * cr + sigf(gr[0]) * tanhf(gr[2]);
                g_c[1][j] = cr2;
                g_h[p ^ 1][1][j] = sigf(gr[3]) * tanhf(cr2);
            }
        }
        grid_sync(round);
    }
    // final states: T_SEQ even -> parity 0.  hf = g_h[0][0], hr = g_h[0][1]

    // ---------------- Small phase C1: common, lat_f, lat_r, vg/jg --------------
    for (int i = tid; i < H_DIM; i += NTHR) {
        shf[i] = g_h[0][0][i];
        shr[i] = g_h[0][1][i];
    }
    __syncthreads();
    {
        const float4* hf4 = (const float4*)shf;
        const float4* hr4 = (const float4*)shr;
        for (int task = wid; task < 1537; task += NWARPS) {
            if (task < CLSD) {
                const float4* w = (const float4*)(cls_W + (size_t)task * 2 * H_DIM);
                float acc = 0.f;
                for (int k = lane; k < H_DIM / 4; k += 32) {
                    float4 w1 = w[k];            float4 a = hf4[k];
                    acc += w1.x*a.x + w1.y*a.y + w1.z*a.z + w1.w*a.w;
                    float4 w2 = w[H_DIM/4 + k];  float4 b = hr4[k];
                    acc += w2.x*b.x + w2.y*b.y + w2.z*b.z + w2.w*b.w;
                }
                acc = warp_sum(acc);
                if (lane == 0) g_common[task] = tanhf(acc + cls_b[task]);
            } else if (task < 1024) {
                const int c = task - 512;
                const float4* w = (const float4*)(latf_W + (size_t)c * H_DIM);
                float acc = 0.f;
                for (int k = lane; k < H_DIM / 4; k += 32) {
                    float4 w1 = w[k]; float4 a = hf4[k];
                    acc += w1.x*a.x + w1.y*a.y + w1.z*a.z + w1.w*a.w;
                }
                acc = warp_sum(acc);
                if (lane == 0) {
                    float v = acc + latf_b[c];
                    g_h0[0][VJD + c] = v;
                    out[OFF_LATF + VJD + c] = v;
                }
            } else if (task < 1536) {
                const int c = task - 1024;
                const float4* w = (const float4*)(latr_W + (size_t)c * H_DIM);
                float acc = 0.f;
                for (int k = lane; k < H_DIM / 4; k += 32) {
                    float4 w1 = w[k]; float4 b = hr4[k];
                    acc += w1.x*b.x + w1.y*b.y + w1.z*b.z + w1.w*b.w;
                }
                acc = warp_sum(acc);
                if (lane == 0) {
                    float v = acc + latr_b[c];
                    g_h0[1][VJD + c] = v;
                    out[OFF_LATR + VJD + c] = v;
                }
            } else {
                const int vgi = Vg[0], jgi = Jg[0];
                for (int k = lane; k < VJD; k += 32) {
                    float v  = emb_Vg[vgi * VJD + k];
                    float jv = emb_Jg[jgi * VJD + k];
                    g_h0[0][k] = v;  g_h0[1][k] = v;
                    out[OFF_LATF + k] = v;  out[OFF_LATR + k] = v;
                    g_h0[0][VJD + LATD + k] = jv;  g_h0[1][VJD + LATD + k] = jv;
                    out[OFF_LATF + VJD + LATD + k] = jv;
                    out[OFF_LATR + VJD + LATD + k] = jv;
                }
            }
        }
    }
    grid_sync(round);

    // ---------------- Small phase C2: mix -------------------------------------
    {
        float* scm = sbuf;
        for (int i = tid; i < CLSD; i += NTHR) scm[i] = g_common[i];
        __syncthreads();
        const float4* cm4 = (const float4*)scm;
        for (int m = wid; m < MIXD; m += NWARPS) {
            const float4* w = (const float4*)(mix_W + (size_t)m * CLSD);
            float acc = 0.f;
            for (int k = lane; k < CLSD / 4; k += 32) {
                float4 w1 = w[k]; float4 a = cm4[k];
                acc += w1.x*a.x + w1.y*a.y + w1.z*a.z + w1.w*a.w;
            }
            acc = warp_sum(acc);
            if (lane == 0) {
                float v = acc + mix_b[m];
                g_h0[0][VJD + LATD + VJD + m] = v;
                g_h0[1][VJD + LATD + VJD + m] = v;
            }
        }
    }
    grid_sync(round);

    // ---------------- Phase C3: decoder state init ----------------------------
    for (int idx = gtid; idx < 2 * E_DIM; idx += GRID_THREADS) {
        int d = idx >> 10, e = idx & 1023;
        float h0v = g_h0[d][e];
        g_dh[0][d][e] = h0v;
        g_dc[d][e]    = h0v;
        // rec_f starts from emb[0] (start), rec_r starts from emb[1] (stop)
        g_dp[0][d][e] = emb[(d == 0 ? 0 : 1) * E_DIM + e];
    }
    grid_sync(round);

    // ---------------- Decoders: 254 steps, two independent LSTMs --------------
    float* spf = sbuf;            // 1024 prev (f)
    float* spr = sbuf + 1024;     // 1024 prev (r)
    float* sdf = sbuf + 2048;     // 1024 hidden (f)
    float* sdr = sbuf + 3072;     // 1024 hidden (r)
    for (int s = 0; s < T_SEQ - 2; ++s) {
        const int p = s & 1;
        for (int i = tid; i < E_DIM; i += NTHR) {
            spf[i] = g_dp[p][0][i];
            spr[i] = g_dp[p][1][i];
            sdf[i] = g_dh[p][0][i];
            sdr[i] = g_dh[p][1][i];
        }
        __syncthreads();

        for (int task = wid; task < 2048; task += NWARPS) {
            const int d = task >> 10;
            const int j = task & 1023;
            const float* Wih = d ? recr_Wih : recf_Wih;
            const float* Whh = d ? recr_Whh : recf_Whh;
            const float* bih = d ? recr_bih : recf_bih;
            const float* bhh = d ? recr_bhh : recf_bhh;
            const float4* xin = (const float4*)(d ? spr : spf);
            const float4* hin = (const float4*)(d ? sdr : sdf);

            float g4[4];
            #pragma unroll
            for (int gx = 0; gx < 4; ++gx) {
                const int row = gx * E_DIM + j;
                const float4* wi = (const float4*)(Wih + (size_t)row * E_DIM);
                const float4* wh = (const float4*)(Whh + (size_t)row * E_DIM);
                float acc = 0.f;
                #pragma unroll 4
                for (int k = lane; k < E_DIM / 4; k += 32) {
                    float4 w = wi[k]; float4 a = xin[k];
                    acc += w.x*a.x + w.y*a.y + w.z*a.z + w.w*a.w;
                    float4 w2 = wh[k]; float4 b = hin[k];
                    acc += w2.x*b.x + w2.y*b.y + w2.z*b.z + w2.w*b.w;
                }
                acc = warp_sum(acc);
                g4[gx] = acc + bih[row] + bhh[row];
            }
            if (lane == 0) {
                float c  = g_dc[d][j];
                float c2 = sigf(g4[1]) * c + sigf(g4[0]) * tanhf(g4[2]);
                g_dc[d][j] = c2;
                float h2 = sigf(g4[3]) * tanhf(c2);
                g_dh[p ^ 1][d][j] = h2;
                g_dp[p ^ 1][d][j] = h2;
                out[(d ? OFF_RECR : OFF_RECF) + (254 - s) * E_DIM + j] = h2;
            }
        }
        grid_sync(round);
    }
}

extern "C" void kernel_launch(void* const* d_in, const int* in_sizes, int n_in,
                              void* d_out, int out_size) {
    (void)in_sizes; (void)n_in; (void)out_size;
    init_kernel<<<1, 1>>>();
    net_kernel<<<NBLK, NTHR>>>(
        (const int*)d_in[0],     // x
        (const int*)d_in[1],     // Vg
        (const int*)d_in[2],     // Jg
        (const float*)d_in[3],   // emb
        (const float*)d_in[4],   // emb_Vg
        (const float*)d_in[5],   // emb_Jg
        (const float*)d_in[6],   // enc_Wih
        (const float*)d_in[7],   // enc_Whh
        (const float*)d_in[8],   // enc_bih
        (const float*)d_in[9],   // enc_bhh
        (const float*)d_in[10],  // cls_W
        (const float*)d_in[11],  // cls_b
        (const float*)d_in[12],  // latf_W
        (const float*)d_in[13],  // latf_b
        (const float*)d_in[14],  // latr_W
        (const float*)d_in[15],  // latr_b
        (const float*)d_in[16],  // mix_W
        (const float*)d_in[17],  // mix_b
        (const float*)d_in[18],  // recf_Wih
        (const float*)d_in[19],  // recf_Whh
        (const float*)d_in[20],  // recf_bih
        (const float*)d_in[21],  // recf_bhh
        (const float*)d_in[22],  // recr_Wih
        (const float*)d_in[23],  // recr_Whh
        (const float*)d_in[24],  // recr_bih
        (const float*)d_in[25],  // recr_bhh
        (float*)d_out);
}

// round 3
// speedup vs baseline: 1.3906x; 1.3906x over previous
#include <cuda_runtime.h>
#include <math.h>

#define T_SEQ 256
#define E_DIM 1024
#define H_DIM 2048
#define LATD  512
#define CLSD  512
#define MIXD  384
#define VJD   64
#define ALPH  32

#define NBLK  148
#define NTHR  512
#define NWARPS (NBLK * (NTHR/32))
#define GRID_THREADS (NBLK * NTHR)

// output layout (float32)
#define OFF_LATF 0
#define OFF_LATR 640
#define OFF_RECF 1280
#define OFF_RECR (1280 + T_SEQ*E_DIM)
#define OFF_EMBF (1280 + 2*T_SEQ*E_DIM)
#define OFF_EMBR (1280 + 3*T_SEQ*E_DIM)

// ---------------- persistent scratch --------------------------------------
__device__ float g_h[2][2][H_DIM];     // encoder hidden ping-pong [parity][dir][j]
__device__ float g_c[2][H_DIM];        // encoder cell [dir][j]
__device__ float g_common[CLSD];
__device__ float g_h0[2][E_DIM];       // decoder initial state [dir][e]
__device__ float g_dh[2][2][E_DIM];    // decoder hidden ping-pong
__device__ float g_dp[2][2][E_DIM];    // decoder prev-output ping-pong
__device__ float g_dc[2][E_DIM];       // decoder cell

__device__ float g_wx[ALPH * 4 * H_DIM];  // WX_sym[sym][gate*H+j]  (1 MB)
__device__ float g_benc[4 * H_DIM];       // enc_bih + enc_bhh
__device__ float g_bdf[4 * E_DIM];        // recf bias sum
__device__ float g_bdr[4 * E_DIM];        // recr bias sum

__device__ unsigned int g_bar_arrive;
__device__ volatile unsigned int g_bar_release;

__global__ void init_kernel() { g_bar_arrive = 0u; g_bar_release = 0u; }

__device__ __forceinline__ float sigf(float x) { return 1.0f / (1.0f + expf(-x)); }

__device__ __forceinline__ void grid_sync(unsigned int& round) {
    __threadfence();
    __syncthreads();
    if (threadIdx.x == 0) {
        round++;
        unsigned int a = atomicAdd(&g_bar_arrive, 1u) + 1u;
        if (a == round * (unsigned)NBLK) {
            g_bar_release = round;
        } else {
            while (g_bar_release < round) { }
        }
    }
    __syncthreads();
}

__device__ __forceinline__ float warp_sum(float v) {
    #pragma unroll
    for (int off = 16; off; off >>= 1) v += __shfl_xor_sync(0xFFFFFFFFu, v, off);
    return v;
}

__device__ __forceinline__ float dot4(float4 w, float4 a) {
    return w.x*a.x + w.y*a.y + w.z*a.z + w.w*a.w;
}

__global__ __launch_bounds__(NTHR, 1)
void net_kernel(const int* __restrict__ x, const int* __restrict__ Vg, const int* __restrict__ Jg,
                const float* __restrict__ emb, const float* __restrict__ emb_Vg, const float* __restrict__ emb_Jg,
                const float* __restrict__ enc_Wih, const float* __restrict__ enc_Whh,
                const float* __restrict__ enc_bih, const float* __restrict__ enc_bhh,
                const float* __restrict__ cls_W, const float* __restrict__ cls_b,
                const float* __restrict__ latf_W, const float* __restrict__ latf_b,
                const float* __restrict__ latr_W, const float* __restrict__ latr_b,
                const float* __restrict__ mix_W, const float* __restrict__ mix_b,
                const float* __restrict__ recf_Wih, const float* __restrict__ recf_Whh,
                const float* __restrict__ recf_bih, const float* __restrict__ recf_bhh,
                const float* __restrict__ recr_Wih, const float* __restrict__ recr_Whh,
                const float* __restrict__ recr_bih, const float* __restrict__ recr_bhh,
                float* __restrict__ out)
{
    __shared__ float sbuf[4096];   // 16 KB staging
    __shared__ int   sx[T_SEQ];
    unsigned int round = 0;

    const int tid  = threadIdx.x;
    const int gtid = blockIdx.x * NTHR + tid;
    const int lane = tid & 31;
    const int wid  = gtid >> 5;   // global warp id

    // ---------------- Phase A -------------------------------------------------
    // A1: WX_sym = enc_Wih @ emb.T  (8192 rows x 32 symbols, fp32)
    for (int row = wid; row < 4 * H_DIM; row += NWARPS) {
        const float4* wr = (const float4*)(enc_Wih + (size_t)row * E_DIM);
        float4 w[8];
        #pragma unroll
        for (int i = 0; i < 8; ++i) w[i] = wr[lane + i * 32];
        for (int sym = 0; sym < ALPH; ++sym) {
            const float4* ev = (const float4*)(emb + (size_t)sym * E_DIM);
            float acc = 0.f;
            #pragma unroll
            for (int i = 0; i < 8; ++i) acc += dot4(w[i], ev[lane + i * 32]);
            acc = warp_sum(acc);
            if (lane == 0) g_wx[sym * 4 * H_DIM + row] = acc;
        }
    }
    // A2: bias sums
    for (int i = gtid; i < 4 * H_DIM; i += GRID_THREADS) g_benc[i] = enc_bih[i] + enc_bhh[i];
    for (int i = gtid; i < 4 * E_DIM; i += GRID_THREADS) {
        g_bdf[i] = recf_bih[i] + recf_bhh[i];
        g_bdr[i] = recr_bih[i] + recr_bhh[i];
    }
    // A3: embedding gather + fixed output edges + encoder state init
    for (int idx = gtid; idx < T_SEQ * E_DIM; idx += GRID_THREADS) {
        int t = idx >> 10, e = idx & 1023;
        float v = emb[x[t] * E_DIM + e];
        out[OFF_EMBF + idx] = v;
        out[OFF_EMBR + (T_SEQ - 1 - t) * E_DIM + e] = v;
    }
    for (int e = gtid; e < E_DIM; e += GRID_THREADS) {
        float e0 = emb[e];             // emb[X_IDX=0] (start)
        float e1 = emb[E_DIM + e];     // emb[B_IDX=1] (stop)
        out[OFF_RECF + e] = e1;
        out[OFF_RECF + 255 * E_DIM + e] = e0;
        out[OFF_RECR + e] = e0;
        out[OFF_RECR + 255 * E_DIM + e] = e1;
    }
    {
        float* hflat = &g_h[0][0][0];
        float* cflat = &g_c[0][0];
        for (int j = gtid; j < 2 * H_DIM; j += GRID_THREADS) { hflat[j] = 0.f; cflat[j] = 0.f; }
    }
    for (int t = tid; t < T_SEQ; t += NTHR) sx[t] = x[t];
    grid_sync(round);

    // ---------------- Encoder: 256 steps, Whh only in the hot loop ------------
    float* shf = sbuf;            // 2048
    float* shr = sbuf + 2048;     // 2048
    for (int t = 0; t < T_SEQ; ++t) {
        const int p = t & 1;
        for (int i = tid; i < H_DIM; i += NTHR) {
            shf[i] = g_h[p][0][i];
            shr[i] = g_h[p][1][i];
        }
        __syncthreads();

        const float4* hf4 = (const float4*)shf;
        const float4* hr4 = (const float4*)shr;
        const int symf = sx[t];
        const int symr = sx[T_SEQ - 1 - t];

        for (int j = wid; j < H_DIM; j += NWARPS) {
            float accf[4] = {0.f, 0.f, 0.f, 0.f};
            float accr[4] = {0.f, 0.f, 0.f, 0.f};
            const float4* wh = (const float4*)enc_Whh;   // row stride H_DIM/4
            #pragma unroll 4
            for (int kk = 0; kk < 16; ++kk) {
                const int k = lane + kk * 32;
                float4 a = hf4[k];
                float4 b = hr4[k];
                #pragma unroll
                for (int gx = 0; gx < 4; ++gx) {
                    float4 w = wh[(size_t)(gx * H_DIM + j) * (H_DIM / 4) + k];
                    accf[gx] += dot4(w, a);
                    accr[gx] += dot4(w, b);
                }
            }
            #pragma unroll
            for (int gx = 0; gx < 4; ++gx) { accf[gx] = warp_sum(accf[gx]); accr[gx] = warp_sum(accr[gx]); }

            if (lane == 0) {
                float gf[4], gr[4];
                #pragma unroll
                for (int gx = 0; gx < 4; ++gx) {
                    const int row = gx * H_DIM + j;
                    float bias = g_benc[row];
                    gf[gx] = accf[gx] + bias + g_wx[symf * 4 * H_DIM + row];
                    gr[gx] = accr[gx] + bias + g_wx[symr * 4 * H_DIM + row];
                }
                float cf = g_c[0][j];
                float cf2 = sigf(gf[1]) * cf + sigf(gf[0]) * tanhf(gf[2]);
                g_c[0][j] = cf2;
                g_h[p ^ 1][0][j] = sigf(gf[3]) * tanhf(cf2);

                float cr = g_c[1][j];
                float cr2 = sigf(gr[1]) * cr + sigf(gr[0]) * tanhf(gr[2]);
                g_c[1][j] = cr2;
                g_h[p ^ 1][1][j] = sigf(gr[3]) * tanhf(cr2);
            }
        }
        grid_sync(round);
    }
    // final states at parity 0: hf = g_h[0][0], hr = g_h[0][1]

    // ---------------- Small phase C1: common, lat_f, lat_r, vg/jg --------------
    for (int i = tid; i < H_DIM; i += NTHR) {
        shf[i] = g_h[0][0][i];
        shr[i] = g_h[0][1][i];
    }
    __syncthreads();
    {
        const float4* hf4 = (const float4*)shf;
        const float4* hr4 = (const float4*)shr;
        for (int task = wid; task < 1537; task += NWARPS) {
            if (task < CLSD) {
                const float4* w = (const float4*)(cls_W + (size_t)task * 2 * H_DIM);
                float acc = 0.f;
                for (int k = lane; k < H_DIM / 4; k += 32) {
                    acc += dot4(w[k], hf4[k]);
                    acc += dot4(w[H_DIM/4 + k], hr4[k]);
                }
                acc = warp_sum(acc);
                if (lane == 0) g_common[task] = tanhf(acc + cls_b[task]);
            } else if (task < 1024) {
                const int c = task - 512;
                const float4* w = (const float4*)(latf_W + (size_t)c * H_DIM);
                float acc = 0.f;
                for (int k = lane; k < H_DIM / 4; k += 32) acc += dot4(w[k], hf4[k]);
                acc = warp_sum(acc);
                if (lane == 0) {
                    float v = acc + latf_b[c];
                    g_h0[0][VJD + c] = v;
                    out[OFF_LATF + VJD + c] = v;
                }
            } else if (task < 1536) {
                const int c = task - 1024;
                const float4* w = (const float4*)(latr_W + (size_t)c * H_DIM);
                float acc = 0.f;
                for (int k = lane; k < H_DIM / 4; k += 32) acc += dot4(w[k], hr4[k]);
                acc = warp_sum(acc);
                if (lane == 0) {
                    float v = acc + latr_b[c];
                    g_h0[1][VJD + c] = v;
                    out[OFF_LATR + VJD + c] = v;
                }
            } else {
                const int vgi = Vg[0], jgi = Jg[0];
                for (int k = lane; k < VJD; k += 32) {
                    float v  = emb_Vg[vgi * VJD + k];
                    float jv = emb_Jg[jgi * VJD + k];
                    g_h0[0][k] = v;  g_h0[1][k] = v;
                    out[OFF_LATF + k] = v;  out[OFF_LATR + k] = v;
                    g_h0[0][VJD + LATD + k] = jv;  g_h0[1][VJD + LATD + k] = jv;
                    out[OFF_LATF + VJD + LATD + k] = jv;
                    out[OFF_LATR + VJD + LATD + k] = jv;
                }
            }
        }
    }
    grid_sync(round);

    // ---------------- Small phase C2: mix -------------------------------------
    {
        float* scm = sbuf;
        for (int i = tid; i < CLSD; i += NTHR) scm[i] = g_common[i];
        __syncthreads();
        const float4* cm4 = (const float4*)scm;
        for (int m = wid; m < MIXD; m += NWARPS) {
            const float4* w = (const float4*)(mix_W + (size_t)m * CLSD);
            float acc = 0.f;
            for (int k = lane; k < CLSD / 4; k += 32) acc += dot4(w[k], cm4[k]);
            acc = warp_sum(acc);
            if (lane == 0) {
                float v = acc + mix_b[m];
                g_h0[0][VJD + LATD + VJD + m] = v;
                g_h0[1][VJD + LATD + VJD + m] = v;
            }
        }
    }
    grid_sync(round);

    // ---------------- Phase C3: decoder state init ----------------------------
    for (int idx = gtid; idx < 2 * E_DIM; idx += GRID_THREADS) {
        int d = idx >> 10, e = idx & 1023;
        float h0v = g_h0[d][e];
        g_dh[0][d][e] = h0v;
        g_dc[d][e]    = h0v;
        g_dp[0][d][e] = emb[(d == 0 ? 0 : 1) * E_DIM + e];
    }
    grid_sync(round);

    // ---------------- Decoders: 254 steps, two independent LSTMs --------------
    float* spf = sbuf;            // 1024 prev (f)
    float* spr = sbuf + 1024;     // 1024 prev (r)
    float* sdf = sbuf + 2048;     // 1024 hidden (f)
    float* sdr = sbuf + 3072;     // 1024 hidden (r)
    for (int s = 0; s < T_SEQ - 2; ++s) {
        const int p = s & 1;
        for (int i = tid; i < E_DIM; i += NTHR) {
            spf[i] = g_dp[p][0][i];
            spr[i] = g_dp[p][1][i];
            sdf[i] = g_dh[p][0][i];
            sdr[i] = g_dh[p][1][i];
        }
        __syncthreads();

        for (int task = wid; task < 2048; task += NWARPS) {
            const int d = task >> 10;
            const int j = task & 1023;
            const float4* wi4 = (const float4*)(d ? recr_Wih : recf_Wih);
            const float4* wh4 = (const float4*)(d ? recr_Whh : recf_Whh);
            const float* bsum = d ? g_bdr : g_bdf;
            const float4* xp4 = (const float4*)(d ? spr : spf);
            const float4* xh4 = (const float4*)(d ? sdr : sdf);

            float acc[4] = {0.f, 0.f, 0.f, 0.f};
            #pragma unroll 4
            for (int kk = 0; kk < 8; ++kk) {
                const int k = lane + kk * 32;
                float4 a = xp4[k];
                float4 h = xh4[k];
                #pragma unroll
                for (int gx = 0; gx < 4; ++gx) {
                    const size_t rb = (size_t)(gx * E_DIM + j) * (E_DIM / 4) + k;
                    acc[gx] += dot4(wi4[rb], a);
                    acc[gx] += dot4(wh4[rb], h);
                }
            }
            #pragma unroll
            for (int gx = 0; gx < 4; ++gx) acc[gx] = warp_sum(acc[gx]);

            if (lane == 0) {
                float g4[4];
                #pragma unroll
                for (int gx = 0; gx < 4; ++gx) g4[gx] = acc[gx] + bsum[gx * E_DIM + j];
                float c  = g_dc[d][j];
                float c2 = sigf(g4[1]) * c + sigf(g4[0]) * tanhf(g4[2]);
                g_dc[d][j] = c2;
                float h2 = sigf(g4[3]) * tanhf(c2);
                g_dh[p ^ 1][d][j] = h2;
                g_dp[p ^ 1][d][j] = h2;
                out[(d ? OFF_RECR : OFF_RECF) + (254 - s) * E_DIM + j] = h2;
            }
        }
        grid_sync(round);
    }
}

extern "C" void kernel_launch(void* const* d_in, const int* in_sizes, int n_in,
                              void* d_out, int out_size) {
    (void)in_sizes; (void)n_in; (void)out_size;
    init_kernel<<<1, 1>>>();
    net_kernel<<<NBLK, NTHR>>>(
        (const int*)d_in[0],     // x
        (const int*)d_in[1],     // Vg
        (const int*)d_in[2],     // Jg
        (const float*)d_in[3],   // emb
        (const float*)d_in[4],   // emb_Vg
        (const float*)d_in[5],   // emb_Jg
        (const float*)d_in[6],   // enc_Wih
        (const float*)d_in[7],   // enc_Whh
        (const float*)d_in[8],   // enc_bih
        (const float*)d_in[9],   // enc_bhh
        (const float*)d_in[10],  // cls_W
        (const float*)d_in[11],  // cls_b
        (const float*)d_in[12],  // latf_W
        (const float*)d_in[13],  // latf_b
        (const float*)d_in[14],  // latr_W
        (const float*)d_in[15],  // latr_b
        (const float*)d_in[16],  // mix_W
        (const float*)d_in[17],  // mix_b
        (const float*)d_in[18],  // recf_Wih
        (const float*)d_in[19],  // recf_Whh
        (const float*)d_in[20],  // recf_bih
        (const float*)d_in[21],  // recf_bhh
        (const float*)d_in[22],  // recr_Wih
        (const float*)d_in[23],  // recr_Whh
        (const float*)d_in[24],  // recr_bih
        (const float*)d_in[25],  // recr_bhh
        (float*)d_out);
}

// round 4
// speedup vs baseline: 1.9369x; 1.3929x over previous
#include <cuda_runtime.h>
#include <math.h>

#define T_SEQ 256
#define E_DIM 1024
#define H_DIM 2048
#define LATD  512
#define CLSD  512
#define MIXD  384
#define VJD   64
#define ALPH  32

#define NBLK  148
#define NTHR  512
#define NWARPS (NBLK * (NTHR/32))
#define GRID_THREADS (NBLK * NTHR)

// output layout (float32)
#define OFF_LATF 0
#define OFF_LATR 640
#define OFF_RECF 1280
#define OFF_RECR (1280 + T_SEQ*E_DIM)
#define OFF_EMBF (1280 + 2*T_SEQ*E_DIM)
#define OFF_EMBR (1280 + 3*T_SEQ*E_DIM)

// ---------------- persistent scratch --------------------------------------
__device__ __align__(16) float g_h[2][2][H_DIM];   // encoder hidden ping-pong
__device__ __align__(16) float g_c[2][H_DIM];      // encoder cell (warp-owned)
__device__ __align__(16) float g_common[CLSD];
__device__ __align__(16) float g_h0[2][E_DIM];     // decoder initial state
__device__ __align__(16) float g_dh[2][2][E_DIM];  // decoder hidden ping-pong
__device__ __align__(16) float g_dp0[2][E_DIM];    // decoder step-0 input (start/stop)
__device__ __align__(16) float g_dc[2][E_DIM];     // decoder cell (warp-owned)

// int16 quantized weights (per-row scale), built in phase A each launch
__device__ uint4 q_eWhh[4 * H_DIM * (H_DIM/8)];    // 8192 rows x 256 uint4 = 32 MB
__device__ uint4 q_dWf[4 * E_DIM * (E_DIM/8)];     // Wih+Whh summed, 4096 x 128 = 8 MB
__device__ uint4 q_dWr[4 * E_DIM * (E_DIM/8)];     // 8 MB
__device__ float s_eW[4 * H_DIM];
__device__ float s_dWf[4 * E_DIM];
__device__ float s_dWr[4 * E_DIM];

__device__ float g_wx[ALPH * 4 * H_DIM];           // WX_sym table (exact Wih path), 1 MB
__device__ float g_benc[4 * H_DIM];                // enc bias sum
__device__ float g_bdf[4 * E_DIM];                 // recf bias sum
__device__ float g_bdr[4 * E_DIM];                 // recr bias sum

__device__ unsigned int g_bar_arrive;
__device__ unsigned int g_pad_sep[64];             // keep counters on separate lines
__device__ unsigned int g_bar_release;

__global__ void init_kernel() { g_bar_arrive = 0u; g_bar_release = 0u; }

__device__ __forceinline__ float sigf(float x) { return 1.0f / (1.0f + expf(-x)); }

// Fast grid barrier: acq_rel atomics only -> NO __threadfence -> no CCTL.IVALL
// -> L1-cached weights survive across steps. All cross-block mutable data must
// be moved with __ldcg/__stcg (L2), which this kernel does.
__device__ __forceinline__ void grid_sync_fast(unsigned int& round) {
    __syncthreads();
    if (threadIdx.x == 0) {
        round++;
        unsigned int prev;
        asm volatile("atom.acq_rel.gpu.global.add.u32 %0, [%1], %2;"
                     : "=r"(prev) : "l"(&g_bar_arrive), "r"(1u) : "memory");
        if (prev + 1u == round * (unsigned)NBLK) {
            asm volatile("st.release.gpu.global.u32 [%0], %1;"
                         :: "l"(&g_bar_release), "r"(round) : "memory");
        } else {
            unsigned int v;
            do {
                asm volatile("ld.acquire.gpu.global.u32 %0, [%1];"
                             : "=r"(v) : "l"(&g_bar_release) : "memory");
            } while (v < round);
        }
    }
    __syncthreads();
}

__device__ __forceinline__ void grid_sync_strong(unsigned int& round) {
    __threadfence();           // phase boundary: full visibility + L1 invalidate
    grid_sync_fast(round);
}

__device__ __forceinline__ float warp_sum(float v) {
    #pragma unroll
    for (int off = 16; off; off >>= 1) v += __shfl_xor_sync(0xFFFFFFFFu, v, off);
    return v;
}

__device__ __forceinline__ float dot4(float4 w, float4 a) {
    return w.x*a.x + w.y*a.y + w.z*a.z + w.w*a.w;
}

// magic-number int16 -> float: value = (float)(u16) - 32768 = signed weight int
#define QMAGIC 0x4B000000u
#define QBIASF 8421376.0f   // 8388608 + 32768

__device__ __forceinline__ float2 unpack2(unsigned int u) {
    float lo = __uint_as_float(__byte_perm(u, QMAGIC, 0x7610)) - QBIASF;
    float hi = __uint_as_float(__byte_perm(u, QMAGIC, 0x7632)) - QBIASF;
    return make_float2(lo, hi);
}

// 8 int16 weights vs 8 activations, two directions sharing the unpack
__device__ __forceinline__ void acc8_dual(uint4 w, float4 af0, float4 af1,
                                          float4 ar0, float4 ar1,
                                          float& f, float& r) {
    float2 e;
    e = unpack2(w.x); f += e.x*af0.x + e.y*af0.y; r += e.x*ar0.x + e.y*ar0.y;
    e = unpack2(w.y); f += e.x*af0.z + e.y*af0.w; r += e.x*ar0.z + e.y*ar0.w;
    e = unpack2(w.z); f += e.x*af1.x + e.y*af1.y; r += e.x*ar1.x + e.y*ar1.y;
    e = unpack2(w.w); f += e.x*af1.z + e.y*af1.w; r += e.x*ar1.z + e.y*ar1.w;
}

__device__ __forceinline__ void acc8(uint4 w, float4 a0, float4 a1, float& s) {
    float2 e;
    e = unpack2(w.x); s += e.x*a0.x + e.y*a0.y;
    e = unpack2(w.y); s += e.x*a0.z + e.y*a0.w;
    e = unpack2(w.z); s += e.x*a1.x + e.y*a1.y;
    e = unpack2(w.w); s += e.x*a1.z + e.y*a1.w;
}

// quantize 4 floats -> 4 biased u16 packed in uint2
__device__ __forceinline__ uint2 quant4(float4 v, float inv) {
    int q0 = __float2int_rn(v.x * inv) + 32768;
    int q1 = __float2int_rn(v.y * inv) + 32768;
    int q2 = __float2int_rn(v.z * inv) + 32768;
    int q3 = __float2int_rn(v.w * inv) + 32768;
    uint2 r;
    r.x = (unsigned)(q0 & 0xFFFF) | ((unsigned)(q1 & 0xFFFF) << 16);
    r.y = (unsigned)(q2 & 0xFFFF) | ((unsigned)(q3 & 0xFFFF) << 16);
    return r;
}

__device__ __forceinline__ float warp_max(float v) {
    #pragma unroll
    for (int off = 16; off; off >>= 1) v = fmaxf(v, __shfl_xor_sync(0xFFFFFFFFu, v, off));
    return v;
}

__global__ __launch_bounds__(NTHR, 1)
void net_kernel(const int* __restrict__ x, const int* __restrict__ Vg, const int* __restrict__ Jg,
                const float* __restrict__ emb, const float* __restrict__ emb_Vg, const float* __restrict__ emb_Jg,
                const float* __restrict__ enc_Wih, const float* __restrict__ enc_Whh,
                const float* __restrict__ enc_bih, const float* __restrict__ enc_bhh,
                const float* __restrict__ cls_W, const float* __restrict__ cls_b,
                const float* __restrict__ latf_W, const float* __restrict__ latf_b,
                const float* __restrict__ latr_W, const float* __restrict__ latr_b,
                const float* __restrict__ mix_W, const float* __restrict__ mix_b,
                const float* __restrict__ recf_Wih, const float* __restrict__ recf_Whh,
                const float* __restrict__ recf_bih, const float* __restrict__ recf_bhh,
                const float* __restrict__ recr_Wih, const float* __restrict__ recr_Whh,
                const float* __restrict__ recr_bih, const float* __restrict__ recr_bhh,
                float* __restrict__ out)
{
    __shared__ __align__(16) float4 sbuf4[1024];   // 16 KB staging
    __shared__ int sx[T_SEQ];
    unsigned int round = 0;

    const int tid  = threadIdx.x;
    const int bx   = blockIdx.x;
    const int gtid = bx * NTHR + tid;
    const int lane = tid & 31;
    const int wid  = gtid >> 5;           // global warp id (for one-shot phases)
    const int wl   = tid >> 5;            // local warp id

    // =========== Phase A: quantize weights + WX table + gather + init =========
    // A1: quantize enc_Whh rows (8192 rows x 2048) with per-row scale
    for (int row = wid; row < 4 * H_DIM; row += NWARPS) {
        const float4* src = (const float4*)(enc_Whh + (size_t)row * H_DIM);
        float m = 0.f;
        #pragma unroll 4
        for (int i = 0; i < 16; ++i) {
            float4 v = src[lane + 32 * i];
            m = fmaxf(m, fmaxf(fmaxf(fabsf(v.x), fabsf(v.y)), fmaxf(fabsf(v.z), fabsf(v.w))));
        }
        m = warp_max(m);
        float inv = (m > 0.f) ? 32767.0f / m : 0.f;
        uint2* dst = (uint2*)(q_eWhh + (size_t)row * (H_DIM/8));
        #pragma unroll 4
        for (int i = 0; i < 16; ++i) {
            int k = lane + 32 * i;
            dst[k] = quant4(src[k], inv);
        }
        if (lane == 0) s_eW[row] = (m > 0.f) ? m / 32767.0f : 0.f;
    }
    // A2: decoder summed mats W+ = Wih + Whh (valid for steps >= 1), quantized
    for (int r = wid; r < 2 * 4 * E_DIM; r += NWARPS) {
        const int d  = r >> 12;
        const int rr = r & 4095;
        const float4* sa = (const float4*)((d ? recr_Wih : recf_Wih) + (size_t)rr * E_DIM);
        const float4* sb = (const float4*)((d ? recr_Whh : recf_Whh) + (size_t)rr * E_DIM);
        float4 w[8];
        float m = 0.f;
        #pragma unroll
        for (int i = 0; i < 8; ++i) {
            float4 a = sa[lane + 32 * i], b = sb[lane + 32 * i];
            w[i] = make_float4(a.x + b.x, a.y + b.y, a.z + b.z, a.w + b.w);
            m = fmaxf(m, fmaxf(fmaxf(fabsf(w[i].x), fabsf(w[i].y)), fmaxf(fabsf(w[i].z), fabsf(w[i].w))));
        }
        m = warp_max(m);
        float inv = (m > 0.f) ? 32767.0f / m : 0.f;
        uint2* dst = (uint2*)((d ? q_dWr : q_dWf) + (size_t)rr * (E_DIM/8));
        #pragma unroll
        for (int i = 0; i < 8; ++i) dst[lane + 32 * i] = quant4(w[i], inv);
        if (lane == 0) (d ? s_dWr : s_dWf)[rr] = (m > 0.f) ? m / 32767.0f : 0.f;
    }
    // A3: WX_sym = enc_Wih @ emb.T (exact fp32 path for encoder inputs)
    for (int row = wid; row < 4 * H_DIM; row += NWARPS) {
        const float4* wr = (const float4*)(enc_Wih + (size_t)row * E_DIM);
        float4 w[8];
        #pragma unroll
        for (int i = 0; i < 8; ++i) w[i] = wr[lane + i * 32];
        for (int sym = 0; sym < ALPH; ++sym) {
            const float4* ev = (const float4*)(emb + (size_t)sym * E_DIM);
            float acc = 0.f;
            #pragma unroll
            for (int i = 0; i < 8; ++i) acc += dot4(w[i], ev[lane + i * 32]);
            acc = warp_sum(acc);
            if (lane == 0) g_wx[sym * 4 * H_DIM + row] = acc;
        }
    }
    // A4: bias sums
    for (int i = gtid; i < 4 * H_DIM; i += GRID_THREADS) g_benc[i] = enc_bih[i] + enc_bhh[i];
    for (int i = gtid; i < 4 * E_DIM; i += GRID_THREADS) {
        g_bdf[i] = recf_bih[i] + recf_bhh[i];
        g_bdr[i] = recr_bih[i] + recr_bhh[i];
    }
    // A5: embedding gather + fixed output edges + encoder state init
    for (int idx = gtid; idx < T_SEQ * E_DIM; idx += GRID_THREADS) {
        int t = idx >> 10, e = idx & 1023;
        float v = emb[x[t] * E_DIM + e];
        out[OFF_EMBF + idx] = v;
        out[OFF_EMBR + (T_SEQ - 1 - t) * E_DIM + e] = v;
    }
    for (int e = gtid; e < E_DIM; e += GRID_THREADS) {
        float e0 = emb[e];             // emb[X_IDX=0]
        float e1 = emb[E_DIM + e];     // emb[B_IDX=1]
        out[OFF_RECF + e] = e1;
        out[OFF_RECF + 255 * E_DIM + e] = e0;
        out[OFF_RECR + e] = e0;
        out[OFF_RECR + 255 * E_DIM + e] = e1;
    }
    {
        float* hflat = &g_h[0][0][0];
        float* cflat = &g_c[0][0];
        for (int j = gtid; j < 2 * H_DIM; j += GRID_THREADS) { hflat[j] = 0.f; cflat[j] = 0.f; }
    }
    for (int t = tid; t < T_SEQ; t += NTHR) sx[t] = x[t];
    grid_sync_strong(round);

    // =========== Encoder: 256 steps, int16 Whh, L1-resident per block =========
    {
        float4* shf4 = sbuf4;          // 512 float4
        float4* shr4 = sbuf4 + 512;
        const int j = wl * NBLK + bx;  // stable block-local task -> L1 reuse
        const uint4* qb = q_eWhh + (size_t)j * (H_DIM/8);
        const size_t gstride = (size_t)H_DIM * (H_DIM/8);   // 2048*256

        for (int t = 0; t < T_SEQ; ++t) {
            const int p = t & 1;
            shf4[tid] = __ldcg(((const float4*)g_h[p][0]) + tid);
            shr4[tid] = __ldcg(((const float4*)g_h[p][1]) + tid);
            __syncthreads();

            if (j < H_DIM) {
                float af[4] = {0.f, 0.f, 0.f, 0.f};
                float ar[4] = {0.f, 0.f, 0.f, 0.f};
                #pragma unroll 2
                for (int i = 0; i < 8; ++i) {
                    const int k = lane + 32 * i;
                    float4 xf0 = shf4[2*k], xf1 = shf4[2*k + 1];
                    float4 xr0 = shr4[2*k], xr1 = shr4[2*k + 1];
                    #pragma unroll
                    for (int gx = 0; gx < 4; ++gx) {
                        uint4 w = qb[(size_t)gx * gstride + k];
                        acc8_dual(w, xf0, xf1, xr0, xr1, af[gx], ar[gx]);
                    }
                }
                #pragma unroll
                for (int gx = 0; gx < 4; ++gx) { af[gx] = warp_sum(af[gx]); ar[gx] = warp_sum(ar[gx]); }

                if (lane == 0) {
                    const int symf = sx[t];
                    const int symr = sx[T_SEQ - 1 - t];
                    float gf[4], gr[4];
                    #pragma unroll
                    for (int gx = 0; gx < 4; ++gx) {
                        const int row = gx * H_DIM + j;
                        float sc = s_eW[row];
                        float bb = g_benc[row];
                        gf[gx] = af[gx] * sc + bb + g_wx[symf * 4 * H_DIM + row];
                        gr[gx] = ar[gx] * sc + bb + g_wx[symr * 4 * H_DIM + row];
                    }
                    float cf = g_c[0][j];
                    float cf2 = sigf(gf[1]) * cf + sigf(gf[0]) * tanhf(gf[2]);
                    g_c[0][j] = cf2;
                    __stcg(&g_h[p ^ 1][0][j], sigf(gf[3]) * tanhf(cf2));

                    float cr = g_c[1][j];
                    float cr2 = sigf(gr[1]) * cr + sigf(gr[0]) * tanhf(gr[2]);
                    g_c[1][j] = cr2;
                    __stcg(&g_h[p ^ 1][1][j], sigf(gr[3]) * tanhf(cr2));
                }
            }
            grid_sync_fast(round);
        }
    }
    // final states at parity 0: hf = g_h[0][0], hr = g_h[0][1]

    // =========== Phase C1: common, lat_f, lat_r, vg/jg ========================
    {
        float4* shf4 = sbuf4;
        float4* shr4 = sbuf4 + 512;
        shf4[tid] = __ldcg(((const float4*)g_h[0][0]) + tid);
        shr4[tid] = __ldcg(((const float4*)g_h[0][1]) + tid);
        __syncthreads();
        const float4* hf4 = shf4;
        const float4* hr4 = shr4;
        for (int task = wid; task < 1537; task += NWARPS) {
            if (task < CLSD) {
                const float4* w = (const float4*)(cls_W + (size_t)task * 2 * H_DIM);
                float acc = 0.f;
                for (int k = lane; k < H_DIM / 4; k += 32) {
                    acc += dot4(w[k], hf4[k]);
                    acc += dot4(w[H_DIM/4 + k], hr4[k]);
                }
                acc = warp_sum(acc);
                if (lane == 0) g_common[task] = tanhf(acc + cls_b[task]);
            } else if (task < 1024) {
                const int c = task - 512;
                const float4* w = (const float4*)(latf_W + (size_t)c * H_DIM);
                float acc = 0.f;
                for (int k = lane; k < H_DIM / 4; k += 32) acc += dot4(w[k], hf4[k]);
                acc = warp_sum(acc);
                if (lane == 0) {
                    float v = acc + latf_b[c];
                    g_h0[0][VJD + c] = v;
                    out[OFF_LATF + VJD + c] = v;
                }
            } else if (task < 1536) {
                const int c = task - 1024;
                const float4* w = (const float4*)(latr_W + (size_t)c * H_DIM);
                float acc = 0.f;
                for (int k = lane; k < H_DIM / 4; k += 32) acc += dot4(w[k], hr4[k]);
                acc = warp_sum(acc);
                if (lane == 0) {
                    float v = acc + latr_b[c];
                    g_h0[1][VJD + c] = v;
                    out[OFF_LATR + VJD + c] = v;
                }
            } else {
                const int vgi = Vg[0], jgi = Jg[0];
                for (int k = lane; k < VJD; k += 32) {
                    float v  = emb_Vg[vgi * VJD + k];
                    float jv = emb_Jg[jgi * VJD + k];
                    g_h0[0][k] = v;  g_h0[1][k] = v;
                    out[OFF_LATF + k] = v;  out[OFF_LATR + k] = v;
                    g_h0[0][VJD + LATD + k] = jv;  g_h0[1][VJD + LATD + k] = jv;
                    out[OFF_LATF + VJD + LATD + k] = jv;
                    out[OFF_LATR + VJD + LATD + k] = jv;
                }
            }
        }
    }
    grid_sync_strong(round);

    // =========== Phase C2: mix ================================================
    {
        float* scm = (float*)sbuf4;
        for (int i = tid; i < CLSD; i += NTHR) scm[i] = __ldcg(&g_common[i]);
        __syncthreads();
        const float4* cm4 = (const float4*)scm;
        for (int m = wid; m < MIXD; m += NWARPS) {
            const float4* w = (const float4*)(mix_W + (size_t)m * CLSD);
            float acc = 0.f;
            for (int k = lane; k < CLSD / 4; k += 32) acc += dot4(w[k], cm4[k]);
            acc = warp_sum(acc);
            if (lane == 0) {
                float v = acc + mix_b[m];
                g_h0[0][VJD + LATD + VJD + m] = v;
                g_h0[1][VJD + LATD + VJD + m] = v;
            }
        }
    }
    grid_sync_strong(round);

    // =========== Phase C3: decoder state init =================================
    for (int idx = gtid; idx < 2 * E_DIM; idx += GRID_THREADS) {
        int d = idx >> 10, e = idx & 1023;
        float h0v = __ldcg(&g_h0[d][e]);
        g_dh[0][d][e] = h0v;
        g_dc[d][e]    = h0v;
        g_dp0[d][e]   = emb[(d == 0 ? 0 : 1) * E_DIM + e];
    }
    grid_sync_strong(round);

    // =========== Decoder step 0 (exact fp32, prev != h only here) =============
    {
        float4* sdf4 = sbuf4;          // 256 each
        float4* sdr4 = sbuf4 + 256;
        float4* spf4 = sbuf4 + 512;
        float4* spr4 = sbuf4 + 768;
        if (tid < 256) {
            sdf4[tid] = __ldcg(((const float4*)g_dh[0][0]) + tid);
            spf4[tid] = __ldcg(((const float4*)g_dp0[0]) + tid);
        } else {
            sdr4[tid - 256] = __ldcg(((const float4*)g_dh[0][1]) + (tid - 256));
            spr4[tid - 256] = __ldcg(((const float4*)g_dp0[1]) + (tid - 256));
        }
        __syncthreads();

        const int t0 = wl * NBLK + bx;
        if (t0 < 2 * E_DIM) {
            const int d = t0 >> 10, j = t0 & 1023;
            const float4* wi = (const float4*)(d ? recr_Wih : recf_Wih);
            const float4* wh = (const float4*)(d ? recr_Whh : recf_Whh);
            const float* bsum = d ? g_bdr : g_bdf;
            const float4* ap = d ? spr4 : spf4;
            const float4* ah = d ? sdr4 : sdf4;
            float acc[4] = {0.f, 0.f, 0.f, 0.f};
            #pragma unroll 2
            for (int i = 0; i < 8; ++i) {
                const int k = lane + 32 * i;
                float4 a = ap[k];
                float4 h = ah[k];
                #pragma unroll
                for (int gx = 0; gx < 4; ++gx) {
                    const size_t rb = (size_t)(gx * E_DIM + j) * (E_DIM/4) + k;
                    acc[gx] += dot4(wi[rb], a) + dot4(wh[rb], h);
                }
            }
            #pragma unroll
            for (int gx = 0; gx < 4; ++gx) acc[gx] = warp_sum(acc[gx]);
            if (lane == 0) {
                float g4[4];
                #pragma unroll
                for (int gx = 0; gx < 4; ++gx) g4[gx] = acc[gx] + bsum[gx * E_DIM + j];
                float c  = g_dc[d][j];
                float c2 = sigf(g4[1]) * c + sigf(g4[0]) * tanhf(g4[2]);
                g_dc[d][j] = c2;
                float h2 = sigf(g4[3]) * tanhf(c2);
                __stcg(&g_dh[1][d][j], h2);
                out[(d ? OFF_RECR : OFF_RECF) + 254 * E_DIM + j] = h2;
            }
        }
        grid_sync_fast(round);
    }

    // =========== Decoder steps 1..253: prev == h, summed int16 W+ =============
    {
        float4* sdf4 = sbuf4;
        float4* sdr4 = sbuf4 + 256;
        const int t0 = wl * NBLK + bx;
        const int d = t0 >> 10, j = t0 & 1023;
        const uint4* qb = (t0 < 2 * E_DIM)
                        ? ((d ? q_dWr : q_dWf) + (size_t)j * (E_DIM/8)) : q_dWf;
        const size_t gstride = (size_t)E_DIM * (E_DIM/8);   // 1024*128
        const float* sW = d ? s_dWr : s_dWf;
        const float* bsum = d ? g_bdr : g_bdf;

        for (int s = 1; s < T_SEQ - 2; ++s) {
            const int p = s & 1;
            if (tid < 256) sdf4[tid] = __ldcg(((const float4*)g_dh[p][0]) + tid);
            else if (tid < 512) sdr4[tid - 256] = __ldcg(((const float4*)g_dh[p][1]) + (tid - 256));
            __syncthreads();

            if (t0 < 2 * E_DIM) {
                const float4* a4 = d ? sdr4 : sdf4;
                float acc[4] = {0.f, 0.f, 0.f, 0.f};
                #pragma unroll
                for (int i = 0; i < 4; ++i) {
                    const int k = lane + 32 * i;
                    float4 a0 = a4[2*k], a1 = a4[2*k + 1];
                    #pragma unroll
                    for (int gx = 0; gx < 4; ++gx) {
                        uint4 w = qb[(size_t)gx * gstride + k];
                        acc8(w, a0, a1, acc[gx]);
                    }
                }
                #pragma unroll
                for (int gx = 0; gx < 4; ++gx) acc[gx] = warp_sum(acc[gx]);
                if (lane == 0) {
                    float g4[4];
                    #pragma unroll
                    for (int gx = 0; gx < 4; ++gx) {
                        const int row = gx * E_DIM + j;
                        g4[gx] = acc[gx] * sW[row] + bsum[row];
                    }
                    float c  = g_dc[d][j];
                    float c2 = sigf(g4[1]) * c + sigf(g4[0]) * tanhf(g4[2]);
                    g_dc[d][j] = c2;
                    float h2 = sigf(g4[3]) * tanhf(c2);
                    __stcg(&g_dh[p ^ 1][d][j], h2);
                    out[(d ? OFF_RECR : OFF_RECF) + (254 - s) * E_DIM + j] = h2;
                }
            }
            grid_sync_fast(round);
        }
    }
}

extern "C" void kernel_launch(void* const* d_in, const int* in_sizes, int n_in,
                              void* d_out, int out_size) {
    (void)in_sizes; (void)n_in; (void)out_size;
    init_kernel<<<1, 1>>>();
    net_kernel<<<NBLK, NTHR>>>(
        (const int*)d_in[0],     // x
        (const int*)d_in[1],     // Vg
        (const int*)d_in[2],     // Jg
        (const float*)d_in[3],   // emb
        (const float*)d_in[4],   // emb_Vg
        (const float*)d_in[5],   // emb_Jg
        (const float*)d_in[6],   // enc_Wih
        (const float*)d_in[7],   // enc_Whh
        (const float*)d_in[8],   // enc_bih
        (const float*)d_in[9],   // enc_bhh
        (const float*)d_in[10],  // cls_W
        (const float*)d_in[11],  // cls_b
        (const float*)d_in[12],  // latf_W
        (const float*)d_in[13],  // latf_b
        (const float*)d_in[14],  // latr_W
        (const float*)d_in[15],  // latr_b
        (const float*)d_in[16],  // mix_W
        (const float*)d_in[17],  // mix_b
        (const float*)d_in[18],  // recf_Wih
        (const float*)d_in[19],  // recf_Whh
        (const float*)d_in[20],  // recf_bih
        (const float*)d_in[21],  // recf_bhh
        (const float*)d_in[22],  // recr_Wih
        (const float*)d_in[23],  // recr_Whh
        (const float*)d_in[24],  // recr_bih
        (const float*)d_in[25],  // recr_bhh
        (float*)d_out);
}